// round 3
// baseline (speedup 1.0000x reference)
#include <cuda_runtime.h>

// SSIM, fully fused, single kernel. X,Y: f32[32,3,512,512] -> scalar mean SSIM.
//
// Per block: tile of 128 output cols x 32 output rows of one channel-image.
// Phase 1: horizontal 11-tap Gaussian of {x,y,x^2,y^2,xy} -> smem [5][42][128],
//          computed with packed fma.rn.f32x2 (column-pair outputs, weight-pair consts).
// Phase 2: vertical 11-tap conv with f32x2 packed column pairs (pairs come packed
//          straight out of 16B smem loads).
// Epilogue folds [-1,1]->[0,1] normalization: mu' = (mu+1)/2, sigma' = sigma/4.
// Block partials -> __device__ array; LAST block (atomic counter) reduces and
// writes the scalar + resets the counter (graph-replay safe, deterministic).

#define TW 128
#define TH 32
#define NHR (TH + 10)   // 42
#define BX 32
#define BY 8
#define NBLOCKS (4 * 16 * 96)

__device__ float g_partials[NBLOCKS];
__device__ unsigned int g_count = 0;

__device__ __forceinline__ unsigned long long pk2(float lo, float hi) {
    unsigned long long r;
    asm("mov.b64 %0, {%1, %2};" : "=l"(r) : "f"(lo), "f"(hi));
    return r;
}
__device__ __forceinline__ void upk2(float& lo, float& hi, unsigned long long v) {
    asm("mov.b64 {%0, %1}, %2;" : "=f"(lo), "=f"(hi) : "l"(v));
}
__device__ __forceinline__ unsigned long long fma2(unsigned long long a,
                                                   unsigned long long b,
                                                   unsigned long long c) {
    unsigned long long d;
    asm("fma.rn.f32x2 %0, %1, %2, %3;" : "=l"(d) : "l"(a), "l"(b), "l"(c));
    return d;
}
__device__ __forceinline__ unsigned long long mul2(unsigned long long a,
                                                   unsigned long long b) {
    unsigned long long d;
    asm("mul.rn.f32x2 %0, %1, %2;" : "=l"(d) : "l"(a), "l"(b));
    return d;
}

// Gaussian(11, sigma=1.5), zero-extended outside [0,10].
__device__ __host__ __forceinline__ constexpr float gwe(int k) {
    return (k == 0 || k == 10) ? 0.00102838f
         : (k == 1 || k == 9)  ? 0.00759876f
         : (k == 2 || k == 8)  ? 0.03600079f
         : (k == 3 || k == 7)  ? 0.10936072f
         : (k == 4 || k == 6)  ? 0.21300555f
         : (k == 5)            ? 0.26601173f
         : 0.0f;
}

__global__ void __launch_bounds__(BX * BY, 2)
ssim_main_kernel(const float* __restrict__ X, const float* __restrict__ Y,
                 float* __restrict__ out, double inv_count) {
    extern __shared__ float sh[];  // [5][NHR][TW] = 107520 B

    const int tx = threadIdx.x;
    const int ty = threadIdx.y;
    const int c0 = blockIdx.x * TW;
    const int r0 = blockIdx.y * TH;
    const long img = blockIdx.z;
    const float* __restrict__ Xi = X + img * (512L * 512L);
    const float* __restrict__ Yi = Y + img * (512L * 512L);
    const int basec = c0 + 4 * tx;

    // ---------------- Phase 1: horizontal pass into smem (f32x2) ----------------
    {
        // WP[a] = {gwe(a), gwe(a-1)} : weight pair for output-col pair (lo=j, hi=j+1)
        unsigned long long WP[12];
#pragma unroll
        for (int a = 0; a < 12; a++) WP[a] = pk2(gwe(a), gwe(a - 1));

        for (int hr = ty; hr < NHR; hr += BY) {
            const int gr = r0 + hr;
            if (gr < 512) {
                float xv[16], yv[16];
                const float* __restrict__ xr = Xi + (long)gr * 512;
                const float* __restrict__ yr = Yi + (long)gr * 512;
#pragma unroll
                for (int q = 0; q < 4; q++) {
                    const int qc = basec + 4 * q;
                    float4 xq, yq;
                    if (qc < 512) {
                        xq = *reinterpret_cast<const float4*>(xr + qc);
                        yq = *reinterpret_cast<const float4*>(yr + qc);
                    } else {
                        xq = make_float4(0.f, 0.f, 0.f, 0.f);
                        yq = make_float4(0.f, 0.f, 0.f, 0.f);
                    }
                    xv[4 * q + 0] = xq.x; xv[4 * q + 1] = xq.y;
                    xv[4 * q + 2] = xq.z; xv[4 * q + 3] = xq.w;
                    yv[4 * q + 0] = yq.x; yv[4 * q + 1] = yq.y;
                    yv[4 * q + 2] = yq.z; yv[4 * q + 3] = yq.w;
                }

                unsigned long long acc2[5][2];
#pragma unroll
                for (int m = 0; m < 5; m++) { acc2[m][0] = 0ull; acc2[m][1] = 0ull; }

#pragma unroll
                for (int t = 0; t < 14; t++) {
                    const unsigned long long xt2 = pk2(xv[t], xv[t]);
                    const unsigned long long yt2 = pk2(yv[t], yv[t]);
                    const unsigned long long pxx2 = mul2(xt2, xt2);
                    const unsigned long long pyy2 = mul2(yt2, yt2);
                    const unsigned long long pxy2 = mul2(xt2, yt2);
#pragma unroll
                    for (int jp = 0; jp < 2; jp++) {
                        const int a = t - 2 * jp;
                        if (a >= 0 && a <= 11) {
                            acc2[0][jp] = fma2(xt2,  WP[a], acc2[0][jp]);
                            acc2[1][jp] = fma2(yt2,  WP[a], acc2[1][jp]);
                            acc2[2][jp] = fma2(pxx2, WP[a], acc2[2][jp]);
                            acc2[3][jp] = fma2(pyy2, WP[a], acc2[3][jp]);
                            acc2[4][jp] = fma2(pxy2, WP[a], acc2[4][jp]);
                        }
                    }
                }
                const int so = hr * TW + 4 * tx;
#pragma unroll
                for (int m = 0; m < 5; m++) {
                    *reinterpret_cast<ulonglong2*>(&sh[m * NHR * TW + so]) =
                        make_ulonglong2(acc2[m][0], acc2[m][1]);
                }
            }
        }
    }
    __syncthreads();

    // ---------------- Phase 2: vertical conv (f32x2), two register-light passes --
    const int lr0 = ty * 4;
    const int scol = 4 * tx;

    // Broadcast weight pairs {w,w}
    unsigned long long WB[11];
#pragma unroll
    for (int k = 0; k < 11; k++) WB[k] = pk2(gwe(k), gwe(k));

    // Pass A: mu1, mu2
    unsigned long long mu[2][4][2];  // [map][vrow][colpair]
#pragma unroll
    for (int m = 0; m < 2; m++)
#pragma unroll
        for (int v = 0; v < 4; v++) { mu[m][v][0] = 0ull; mu[m][v][1] = 0ull; }

#pragma unroll
    for (int i = 0; i < 14; i++) {
        const ulonglong2 a = *reinterpret_cast<const ulonglong2*>(&sh[(0 * NHR + lr0 + i) * TW + scol]);
        const ulonglong2 b = *reinterpret_cast<const ulonglong2*>(&sh[(1 * NHR + lr0 + i) * TW + scol]);
#pragma unroll
        for (int v = 0; v < 4; v++) {
            const int k = i - v;
            if (k >= 0 && k <= 10) {
                mu[0][v][0] = fma2(a.x, WB[k], mu[0][v][0]);
                mu[0][v][1] = fma2(a.y, WB[k], mu[0][v][1]);
                mu[1][v][0] = fma2(b.x, WB[k], mu[1][v][0]);
                mu[1][v][1] = fma2(b.y, WB[k], mu[1][v][1]);
            }
        }
    }

    // Pass B: xx, yy, xy
    unsigned long long sg[3][4][2];
#pragma unroll
    for (int m = 0; m < 3; m++)
#pragma unroll
        for (int v = 0; v < 4; v++) { sg[m][v][0] = 0ull; sg[m][v][1] = 0ull; }

#pragma unroll
    for (int i = 0; i < 14; i++) {
        const ulonglong2 a = *reinterpret_cast<const ulonglong2*>(&sh[(2 * NHR + lr0 + i) * TW + scol]);
        const ulonglong2 b = *reinterpret_cast<const ulonglong2*>(&sh[(3 * NHR + lr0 + i) * TW + scol]);
        const ulonglong2 d = *reinterpret_cast<const ulonglong2*>(&sh[(4 * NHR + lr0 + i) * TW + scol]);
#pragma unroll
        for (int v = 0; v < 4; v++) {
            const int k = i - v;
            if (k >= 0 && k <= 10) {
                sg[0][v][0] = fma2(a.x, WB[k], sg[0][v][0]);
                sg[0][v][1] = fma2(a.y, WB[k], sg[0][v][1]);
                sg[1][v][0] = fma2(b.x, WB[k], sg[1][v][0]);
                sg[1][v][1] = fma2(b.y, WB[k], sg[1][v][1]);
                sg[2][v][0] = fma2(d.x, WB[k], sg[2][v][0]);
                sg[2][v][1] = fma2(d.y, WB[k], sg[2][v][1]);
            }
        }
    }

    // ---------------- Epilogue + reduction ----------------
    float lsum = 0.0f;
    const float C1 = 1e-4f;      // (0.01)^2
    const float C2x4 = 0.0036f;  // 4*(0.03)^2
#pragma unroll
    for (int v = 0; v < 4; v++) {
        const int orow = r0 + lr0 + v;
#pragma unroll
        for (int p = 0; p < 2; p++) {
            float m1a, m1b, m2a, m2b, xxa, xxb, yya, yyb, xya, xyb;
            upk2(m1a, m1b, mu[0][v][p]);
            upk2(m2a, m2b, mu[1][v][p]);
            upk2(xxa, xxb, sg[0][v][p]);
            upk2(yya, yyb, sg[1][v][p]);
            upk2(xya, xyb, sg[2][v][p]);
#pragma unroll
            for (int h = 0; h < 2; h++) {
                const float m1 = h ? m1b : m1a;
                const float m2 = h ? m2b : m2a;
                const float xx = h ? xxb : xxa;
                const float yy = h ? yyb : yya;
                const float xy = h ? xyb : xya;
                const int ocol = basec + 2 * p + h;
                const float s1  = fmaf(-m1, m1, xx);
                const float s2  = fmaf(-m2, m2, yy);
                const float s12 = fmaf(-m1, m2, xy);
                const float m1p = fmaf(0.5f, m1, 0.5f);
                const float m2p = fmaf(0.5f, m2, 0.5f);
                const float csn = fmaf(2.0f, s12, C2x4);
                const float csd = s1 + s2 + C2x4;
                const float t = m1p * m2p;
                const float ln = fmaf(2.0f, t, C1);
                const float ld = fmaf(m1p, m1p, fmaf(m2p, m2p, C1));
                const float ssim = (csn * ln) * __fdividef(1.0f, csd * ld);
                lsum += (orow < 502 && ocol < 502) ? ssim : 0.0f;
            }
        }
    }

#pragma unroll
    for (int off = 16; off > 0; off >>= 1)
        lsum += __shfl_xor_sync(0xffffffffu, lsum, off);

    __shared__ float wsum[BY];
    __shared__ bool is_last;
    if (tx == 0) wsum[ty] = lsum;
    __syncthreads();
    if (tx == 0 && ty == 0) {
        float b = 0.0f;
#pragma unroll
        for (int w = 0; w < BY; w++) b += wsum[w];
        const int bi = blockIdx.x + gridDim.x * (blockIdx.y + gridDim.y * blockIdx.z);
        g_partials[bi] = b;
        __threadfence();
        const unsigned int n = atomicAdd(&g_count, 1u);
        is_last = (n == (unsigned int)(NBLOCKS - 1));
    }
    __syncthreads();

    if (is_last) {
        __threadfence();  // acquire: see all partials
        const int tid = ty * BX + tx;
        double s = 0.0;
        for (int i = tid; i < NBLOCKS; i += BX * BY)
            s += (double)g_partials[i];
#pragma unroll
        for (int off = 16; off > 0; off >>= 1)
            s += __shfl_xor_sync(0xffffffffu, s, off);
        __shared__ double sd[BY];
        if (tx == 0) sd[ty] = s;
        __syncthreads();
        if (tx == 0 && ty == 0) {
            double tot = 0.0;
#pragma unroll
            for (int w = 0; w < BY; w++) tot += sd[w];
            out[0] = (float)(tot * inv_count);
            g_count = 0;  // reset for next graph replay
        }
    }
}

extern "C" void kernel_launch(void* const* d_in, const int* in_sizes, int n_in,
                              void* d_out, int out_size) {
    const float* X = (const float*)d_in[0];
    const float* Y = (const float*)d_in[1];
    float* out = (float*)d_out;

    const int images = in_sizes[0] / (512 * 512);  // 96
    const double count = (double)images * 502.0 * 502.0;

    const size_t smem = 5 * NHR * TW * sizeof(float);  // 107520 B
    cudaFuncSetAttribute(ssim_main_kernel,
                         cudaFuncAttributeMaxDynamicSharedMemorySize, (int)smem);

    dim3 grid(4, (502 + TH - 1) / TH, images);  // 4 x 16 x 96 = 6144 blocks
    dim3 block(BX, BY);
    ssim_main_kernel<<<grid, block, smem>>>(X, Y, out, 1.0 / count);
}

// round 4
// speedup vs baseline: 1.0006x; 1.0006x over previous
#include <cuda_runtime.h>

// SSIM, fully fused, single kernel. X,Y: f32[32,3,512,512] -> scalar mean SSIM.
//
// Per block: tile of 128 output cols x 32 output rows of one channel-image.
// Phase 1: horizontal 11-tap Gaussian of {x,y,x^2,y^2,xy} -> smem [5][42][128].
// Phase 2: vertical 11-tap conv, two register-light passes (mu's, then sigmas).
// ALL conv FMAs are forced to the FFMA-imm SASS form (rt_SMSP=1, 2x throughput of
// 3-reg FFMA) via inline PTX with 0f-hex weight literals.
// Epilogue folds [-1,1]->[0,1] normalization: mu' = (mu+1)/2, sigma' = sigma/4.
// Block partials -> __device__ array; last block reduces and writes the scalar.

#define TW 128
#define TH 32
#define NHR (TH + 10)   // 42
#define BX 32
#define BY 8
#define NBLOCKS (4 * 16 * 96)

__device__ float g_partials[NBLOCKS];
__device__ unsigned int g_count = 0;

// Gaussian(11, sigma=1.5) weights as f32 hex:
// w0=0.00102838 w1=0.00759876 w2=0.03600079 w3=0.10936072 w4=0.21300555 w5=0.26601173
// acc = v * w[k] + acc, with w[k] as an IMMEDIATE multiplier (FFMA-imm, rt=1).
// k is a compile-time constant after unrolling -> switch folds to one instruction.
__device__ __forceinline__ void fmaw(const int k, const float v, float& a) {
    switch (k) {
    case 0:  asm("fma.rn.f32 %0, %1, 0f3A86CAB5, %0;" : "+f"(a) : "f"(v)); break;
    case 1:  asm("fma.rn.f32 %0, %1, 0f3BF8FF05, %0;" : "+f"(a) : "f"(v)); break;
    case 2:  asm("fma.rn.f32 %0, %1, 0f3D137590, %0;" : "+f"(a) : "f"(v)); break;
    case 3:  asm("fma.rn.f32 %0, %1, 0f3DDFF883, %0;" : "+f"(a) : "f"(v)); break;
    case 4:  asm("fma.rn.f32 %0, %1, 0f3E5A1E20, %0;" : "+f"(a) : "f"(v)); break;
    case 5:  asm("fma.rn.f32 %0, %1, 0f3E8832B1, %0;" : "+f"(a) : "f"(v)); break;
    case 6:  asm("fma.rn.f32 %0, %1, 0f3E5A1E20, %0;" : "+f"(a) : "f"(v)); break;
    case 7:  asm("fma.rn.f32 %0, %1, 0f3DDFF883, %0;" : "+f"(a) : "f"(v)); break;
    case 8:  asm("fma.rn.f32 %0, %1, 0f3D137590, %0;" : "+f"(a) : "f"(v)); break;
    case 9:  asm("fma.rn.f32 %0, %1, 0f3BF8FF05, %0;" : "+f"(a) : "f"(v)); break;
    case 10: asm("fma.rn.f32 %0, %1, 0f3A86CAB5, %0;" : "+f"(a) : "f"(v)); break;
    default: break;
    }
}

__device__ __forceinline__ void pf_l2(const void* p) {
    asm volatile("prefetch.global.L2 [%0];" :: "l"(p));
}

__global__ void __launch_bounds__(BX * BY, 2)
ssim_main_kernel(const float* __restrict__ X, const float* __restrict__ Y,
                 float* __restrict__ out, double inv_count) {
    extern __shared__ float sh[];  // [5][NHR][TW] = 107520 B

    const int tx = threadIdx.x;
    const int ty = threadIdx.y;
    const int c0 = blockIdx.x * TW;
    const int r0 = blockIdx.y * TH;
    const long img = blockIdx.z;
    const float* __restrict__ Xi = X + img * (512L * 512L);
    const float* __restrict__ Yi = Y + img * (512L * 512L);
    const int basec = c0 + 4 * tx;

    // ---------------- Phase 1: horizontal pass into smem ----------------
    for (int hr = ty; hr < NHR; hr += BY) {
        const int gr = r0 + hr;
        if (gr < 512) {
            const float* __restrict__ xr = Xi + (long)gr * 512;
            const float* __restrict__ yr = Yi + (long)gr * 512;
            // L2 prefetch of next row this thread will process
            if (hr + BY < NHR && gr + BY < 512) {
                pf_l2(xr + BY * 512 + basec);
                pf_l2(yr + BY * 512 + basec);
            }
            float xv[16], yv[16];
#pragma unroll
            for (int q = 0; q < 4; q++) {
                const int qc = basec + 4 * q;
                float4 xq, yq;
                if (qc < 512) {
                    xq = *reinterpret_cast<const float4*>(xr + qc);
                    yq = *reinterpret_cast<const float4*>(yr + qc);
                } else {
                    xq = make_float4(0.f, 0.f, 0.f, 0.f);
                    yq = make_float4(0.f, 0.f, 0.f, 0.f);
                }
                xv[4 * q + 0] = xq.x; xv[4 * q + 1] = xq.y;
                xv[4 * q + 2] = xq.z; xv[4 * q + 3] = xq.w;
                yv[4 * q + 0] = yq.x; yv[4 * q + 1] = yq.y;
                yv[4 * q + 2] = yq.z; yv[4 * q + 3] = yq.w;
            }
            float ax[4], ay[4], axx[4], ayy[4], axy[4];
#pragma unroll
            for (int j = 0; j < 4; j++) {
                ax[j] = 0.f; ay[j] = 0.f; axx[j] = 0.f; ayy[j] = 0.f; axy[j] = 0.f;
            }
#pragma unroll
            for (int t = 0; t < 14; t++) {
                const float xt = xv[t], yt = yv[t];
                const float pxx = xt * xt;
                const float pyy = yt * yt;
                const float pxy = xt * yt;
#pragma unroll
                for (int j = 0; j < 4; j++) {
                    const int k = t - j;
                    if (k >= 0 && k <= 10) {
                        fmaw(k, xt,  ax[j]);
                        fmaw(k, yt,  ay[j]);
                        fmaw(k, pxx, axx[j]);
                        fmaw(k, pyy, ayy[j]);
                        fmaw(k, pxy, axy[j]);
                    }
                }
            }
            const int so = hr * TW + 4 * tx;
            *reinterpret_cast<float4*>(&sh[0 * NHR * TW + so]) = make_float4(ax[0], ax[1], ax[2], ax[3]);
            *reinterpret_cast<float4*>(&sh[1 * NHR * TW + so]) = make_float4(ay[0], ay[1], ay[2], ay[3]);
            *reinterpret_cast<float4*>(&sh[2 * NHR * TW + so]) = make_float4(axx[0], axx[1], axx[2], axx[3]);
            *reinterpret_cast<float4*>(&sh[3 * NHR * TW + so]) = make_float4(ayy[0], ayy[1], ayy[2], ayy[3]);
            *reinterpret_cast<float4*>(&sh[4 * NHR * TW + so]) = make_float4(axy[0], axy[1], axy[2], axy[3]);
        }
    }
    __syncthreads();

    // ---------------- Phase 2A: vertical conv of mu1, mu2 ----------------
    const int lr0 = ty * 4;
    const int scol = 4 * tx;

    float mu1[4][4], mu2[4][4];
#pragma unroll
    for (int v = 0; v < 4; v++)
#pragma unroll
        for (int c = 0; c < 4; c++) { mu1[v][c] = 0.f; mu2[v][c] = 0.f; }

#pragma unroll
    for (int i = 0; i < 14; i++) {
        const float4 a = *reinterpret_cast<const float4*>(&sh[(0 * NHR + lr0 + i) * TW + scol]);
        const float4 b = *reinterpret_cast<const float4*>(&sh[(1 * NHR + lr0 + i) * TW + scol]);
        const float av[4] = {a.x, a.y, a.z, a.w};
        const float bv[4] = {b.x, b.y, b.z, b.w};
#pragma unroll
        for (int v = 0; v < 4; v++) {
            const int k = i - v;
            if (k >= 0 && k <= 10) {
#pragma unroll
                for (int c = 0; c < 4; c++) {
                    fmaw(k, av[c], mu1[v][c]);
                    fmaw(k, bv[c], mu2[v][c]);
                }
            }
        }
    }

    // ---------------- Phase 2B: vertical conv of xx, yy, xy ----------------
    float sxx[4][4], syy[4][4], sxy[4][4];
#pragma unroll
    for (int v = 0; v < 4; v++)
#pragma unroll
        for (int c = 0; c < 4; c++) { sxx[v][c] = 0.f; syy[v][c] = 0.f; sxy[v][c] = 0.f; }

#pragma unroll
    for (int i = 0; i < 14; i++) {
        const float4 a = *reinterpret_cast<const float4*>(&sh[(2 * NHR + lr0 + i) * TW + scol]);
        const float4 b = *reinterpret_cast<const float4*>(&sh[(3 * NHR + lr0 + i) * TW + scol]);
        const float4 d = *reinterpret_cast<const float4*>(&sh[(4 * NHR + lr0 + i) * TW + scol]);
        const float av[4] = {a.x, a.y, a.z, a.w};
        const float bv[4] = {b.x, b.y, b.z, b.w};
        const float dv[4] = {d.x, d.y, d.z, d.w};
#pragma unroll
        for (int v = 0; v < 4; v++) {
            const int k = i - v;
            if (k >= 0 && k <= 10) {
#pragma unroll
                for (int c = 0; c < 4; c++) {
                    fmaw(k, av[c], sxx[v][c]);
                    fmaw(k, bv[c], syy[v][c]);
                    fmaw(k, dv[c], sxy[v][c]);
                }
            }
        }
    }

    // ---------------- Epilogue + reduction ----------------
    float lsum = 0.0f;
    const float C1 = 1e-4f;      // (0.01)^2
    const float C2x4 = 0.0036f;  // 4*(0.03)^2
#pragma unroll
    for (int v = 0; v < 4; v++) {
        const int orow = r0 + lr0 + v;
#pragma unroll
        for (int c = 0; c < 4; c++) {
            const int ocol = basec + c;
            const float m1 = mu1[v][c];
            const float m2 = mu2[v][c];
            const float s1  = fmaf(-m1, m1, sxx[v][c]);
            const float s2  = fmaf(-m2, m2, syy[v][c]);
            const float s12 = fmaf(-m1, m2, sxy[v][c]);
            const float m1p = fmaf(0.5f, m1, 0.5f);
            const float m2p = fmaf(0.5f, m2, 0.5f);
            const float csn = fmaf(2.0f, s12, C2x4);
            const float csd = s1 + s2 + C2x4;
            const float t = m1p * m2p;
            const float ln = fmaf(2.0f, t, C1);
            const float ld = fmaf(m1p, m1p, fmaf(m2p, m2p, C1));
            const float ssim = (csn * ln) * __fdividef(1.0f, csd * ld);
            lsum += (orow < 502 && ocol < 502) ? ssim : 0.0f;
        }
    }

#pragma unroll
    for (int off = 16; off > 0; off >>= 1)
        lsum += __shfl_xor_sync(0xffffffffu, lsum, off);

    __shared__ float wsum[BY];
    __shared__ bool is_last;
    if (tx == 0) wsum[ty] = lsum;
    __syncthreads();
    if (tx == 0 && ty == 0) {
        float b = 0.0f;
#pragma unroll
        for (int w = 0; w < BY; w++) b += wsum[w];
        const int bi = blockIdx.x + gridDim.x * (blockIdx.y + gridDim.y * blockIdx.z);
        g_partials[bi] = b;
        __threadfence();
        const unsigned int n = atomicAdd(&g_count, 1u);
        is_last = (n == (unsigned int)(NBLOCKS - 1));
    }
    __syncthreads();

    if (is_last) {
        __threadfence();
        const int tid = ty * BX + tx;
        double s = 0.0;
        for (int i = tid; i < NBLOCKS; i += BX * BY)
            s += (double)g_partials[i];
#pragma unroll
        for (int off = 16; off > 0; off >>= 1)
            s += __shfl_xor_sync(0xffffffffu, s, off);
        __shared__ double sd[BY];
        if (tx == 0) sd[ty] = s;
        __syncthreads();
        if (tx == 0 && ty == 0) {
            double tot = 0.0;
#pragma unroll
            for (int w = 0; w < BY; w++) tot += sd[w];
            out[0] = (float)(tot * inv_count);
            g_count = 0;  // reset for next graph replay
        }
    }
}

extern "C" void kernel_launch(void* const* d_in, const int* in_sizes, int n_in,
                              void* d_out, int out_size) {
    const float* X = (const float*)d_in[0];
    const float* Y = (const float*)d_in[1];
    float* out = (float*)d_out;

    const int images = in_sizes[0] / (512 * 512);  // 96
    const double count = (double)images * 502.0 * 502.0;

    const size_t smem = 5 * NHR * TW * sizeof(float);  // 107520 B
    cudaFuncSetAttribute(ssim_main_kernel,
                         cudaFuncAttributeMaxDynamicSharedMemorySize, (int)smem);

    dim3 grid(4, (502 + TH - 1) / TH, images);  // 6144 blocks
    dim3 block(BX, BY);
    ssim_main_kernel<<<grid, block, smem>>>(X, Y, out, 1.0 / count);
}

// round 5
// speedup vs baseline: 1.1306x; 1.1299x over previous
#include <cuda_runtime.h>

// SSIM, fully fused, single kernel. X,Y: f32[32,3,512,512] -> scalar mean SSIM.
//
// Retile for occupancy: TW=64 x TH=48 tiles, smem [5][58][64] = 74.25KB -> 3 CTAs/SM.
// Phase 1: horizontal 11-tap Gaussian of {x,y,x^2,y^2,xy} -> smem.
// Phase 2: vertical 11-tap conv, single pass, 3 vrows x 4 cols per thread.
// Conv FMAs forced to FFMA-imm SASS form (rt_SMSP=1) via 0f-hex weight literals.
// Epilogue folds [-1,1]->[0,1]: mu' = (mu+1)/2, sigma' = sigma/4.
// Block partials -> __device__ array; last block reduces, writes scalar, resets.

#define TW 64
#define TH 48
#define NHR (TH + 10)   // 58
#define BX 16
#define BY 16
#define NTHR (BX * BY)  // 256
#define GX 8            // 512/64
#define GY 11           // ceil(502/48)
#define GZ 96
#define NBLOCKS (GX * GY * GZ)

__device__ float g_partials[NBLOCKS];
__device__ unsigned int g_count = 0;

// acc += v * w[k], w[k] an immediate multiplier (FFMA-imm form, rt=1).
__device__ __forceinline__ void fmaw(const int k, const float v, float& a) {
    switch (k) {
    case 0:  asm("fma.rn.f32 %0, %1, 0f3A86CAB5, %0;" : "+f"(a) : "f"(v)); break;
    case 1:  asm("fma.rn.f32 %0, %1, 0f3BF8FF05, %0;" : "+f"(a) : "f"(v)); break;
    case 2:  asm("fma.rn.f32 %0, %1, 0f3D137590, %0;" : "+f"(a) : "f"(v)); break;
    case 3:  asm("fma.rn.f32 %0, %1, 0f3DDFF883, %0;" : "+f"(a) : "f"(v)); break;
    case 4:  asm("fma.rn.f32 %0, %1, 0f3E5A1E20, %0;" : "+f"(a) : "f"(v)); break;
    case 5:  asm("fma.rn.f32 %0, %1, 0f3E8832B1, %0;" : "+f"(a) : "f"(v)); break;
    case 6:  asm("fma.rn.f32 %0, %1, 0f3E5A1E20, %0;" : "+f"(a) : "f"(v)); break;
    case 7:  asm("fma.rn.f32 %0, %1, 0f3DDFF883, %0;" : "+f"(a) : "f"(v)); break;
    case 8:  asm("fma.rn.f32 %0, %1, 0f3D137590, %0;" : "+f"(a) : "f"(v)); break;
    case 9:  asm("fma.rn.f32 %0, %1, 0f3BF8FF05, %0;" : "+f"(a) : "f"(v)); break;
    case 10: asm("fma.rn.f32 %0, %1, 0f3A86CAB5, %0;" : "+f"(a) : "f"(v)); break;
    default: break;
    }
}

__global__ void __launch_bounds__(NTHR, 3)
ssim_main_kernel(const float* __restrict__ X, const float* __restrict__ Y,
                 float* __restrict__ out, double inv_count) {
    extern __shared__ float sh[];  // [5][NHR][TW] = 74240 B

    const int tx = threadIdx.x;            // 0..15, 4 cols each
    const int ty = threadIdx.y;            // 0..15
    const int c0 = blockIdx.x * TW;
    const int r0 = blockIdx.y * TH;
    const long img = blockIdx.z;
    const float* __restrict__ Xi = X + img * (512L * 512L);
    const float* __restrict__ Yi = Y + img * (512L * 512L);
    const int basec = c0 + 4 * tx;

    // ---------------- Phase 1: horizontal pass into smem ----------------
    for (int hr = ty; hr < NHR; hr += BY) {
        const int gr = r0 + hr;
        float xv[16], yv[16];
        const float* __restrict__ xr = Xi + (long)gr * 512;
        const float* __restrict__ yr = Yi + (long)gr * 512;
        const bool rok = (gr < 512);
#pragma unroll
        for (int q = 0; q < 4; q++) {
            const int qc = basec + 4 * q;
            float4 xq, yq;
            if (rok && qc < 512) {
                xq = *reinterpret_cast<const float4*>(xr + qc);
                yq = *reinterpret_cast<const float4*>(yr + qc);
            } else {
                xq = make_float4(0.f, 0.f, 0.f, 0.f);
                yq = make_float4(0.f, 0.f, 0.f, 0.f);
            }
            xv[4 * q + 0] = xq.x; xv[4 * q + 1] = xq.y;
            xv[4 * q + 2] = xq.z; xv[4 * q + 3] = xq.w;
            yv[4 * q + 0] = yq.x; yv[4 * q + 1] = yq.y;
            yv[4 * q + 2] = yq.z; yv[4 * q + 3] = yq.w;
        }
        float ax[4], ay[4], axx[4], ayy[4], axy[4];
#pragma unroll
        for (int j = 0; j < 4; j++) {
            ax[j] = 0.f; ay[j] = 0.f; axx[j] = 0.f; ayy[j] = 0.f; axy[j] = 0.f;
        }
#pragma unroll
        for (int t = 0; t < 14; t++) {
            const float xt = xv[t], yt = yv[t];
            const float pxx = xt * xt;
            const float pyy = yt * yt;
            const float pxy = xt * yt;
#pragma unroll
            for (int j = 0; j < 4; j++) {
                const int k = t - j;
                if (k >= 0 && k <= 10) {
                    fmaw(k, xt,  ax[j]);
                    fmaw(k, yt,  ay[j]);
                    fmaw(k, pxx, axx[j]);
                    fmaw(k, pyy, ayy[j]);
                    fmaw(k, pxy, axy[j]);
                }
            }
        }
        const int so = hr * TW + 4 * tx;
        *reinterpret_cast<float4*>(&sh[0 * NHR * TW + so]) = make_float4(ax[0], ax[1], ax[2], ax[3]);
        *reinterpret_cast<float4*>(&sh[1 * NHR * TW + so]) = make_float4(ay[0], ay[1], ay[2], ay[3]);
        *reinterpret_cast<float4*>(&sh[2 * NHR * TW + so]) = make_float4(axx[0], axx[1], axx[2], axx[3]);
        *reinterpret_cast<float4*>(&sh[3 * NHR * TW + so]) = make_float4(ayy[0], ayy[1], ayy[2], ayy[3]);
        *reinterpret_cast<float4*>(&sh[4 * NHR * TW + so]) = make_float4(axy[0], axy[1], axy[2], axy[3]);
    }
    __syncthreads();

    // ---------------- Phase 2: vertical conv, single pass, 3 vrows x 4 cols ------
    const int lr0 = ty * 3;   // 16 * 3 = 48 rows
    const int scol = 4 * tx;

    float mu1[3][4], mu2[3][4], sxx[3][4], syy[3][4], sxy[3][4];
#pragma unroll
    for (int v = 0; v < 3; v++)
#pragma unroll
        for (int c = 0; c < 4; c++) {
            mu1[v][c] = 0.f; mu2[v][c] = 0.f;
            sxx[v][c] = 0.f; syy[v][c] = 0.f; sxy[v][c] = 0.f;
        }

#pragma unroll
    for (int i = 0; i < 13; i++) {   // taps for vrows 0..2: i = v + k, k in 0..10
        const int roff = (lr0 + i) * TW + scol;
        {
            const float4 a = *reinterpret_cast<const float4*>(&sh[0 * NHR * TW + roff]);
            const float av[4] = {a.x, a.y, a.z, a.w};
#pragma unroll
            for (int v = 0; v < 3; v++) {
                const int k = i - v;
                if (k >= 0 && k <= 10)
#pragma unroll
                    for (int c = 0; c < 4; c++) fmaw(k, av[c], mu1[v][c]);
            }
        }
        {
            const float4 a = *reinterpret_cast<const float4*>(&sh[1 * NHR * TW + roff]);
            const float av[4] = {a.x, a.y, a.z, a.w};
#pragma unroll
            for (int v = 0; v < 3; v++) {
                const int k = i - v;
                if (k >= 0 && k <= 10)
#pragma unroll
                    for (int c = 0; c < 4; c++) fmaw(k, av[c], mu2[v][c]);
            }
        }
        {
            const float4 a = *reinterpret_cast<const float4*>(&sh[2 * NHR * TW + roff]);
            const float av[4] = {a.x, a.y, a.z, a.w};
#pragma unroll
            for (int v = 0; v < 3; v++) {
                const int k = i - v;
                if (k >= 0 && k <= 10)
#pragma unroll
                    for (int c = 0; c < 4; c++) fmaw(k, av[c], sxx[v][c]);
            }
        }
        {
            const float4 a = *reinterpret_cast<const float4*>(&sh[3 * NHR * TW + roff]);
            const float av[4] = {a.x, a.y, a.z, a.w};
#pragma unroll
            for (int v = 0; v < 3; v++) {
                const int k = i - v;
                if (k >= 0 && k <= 10)
#pragma unroll
                    for (int c = 0; c < 4; c++) fmaw(k, av[c], syy[v][c]);
            }
        }
        {
            const float4 a = *reinterpret_cast<const float4*>(&sh[4 * NHR * TW + roff]);
            const float av[4] = {a.x, a.y, a.z, a.w};
#pragma unroll
            for (int v = 0; v < 3; v++) {
                const int k = i - v;
                if (k >= 0 && k <= 10)
#pragma unroll
                    for (int c = 0; c < 4; c++) fmaw(k, av[c], sxy[v][c]);
            }
        }
    }

    // ---------------- Epilogue + reduction ----------------
    float lsum = 0.0f;
    const float C1 = 1e-4f;      // (0.01)^2
    const float C2x4 = 0.0036f;  // 4*(0.03)^2
#pragma unroll
    for (int v = 0; v < 3; v++) {
        const int orow = r0 + lr0 + v;
#pragma unroll
        for (int c = 0; c < 4; c++) {
            const int ocol = basec + c;
            const float m1 = mu1[v][c];
            const float m2 = mu2[v][c];
            const float s1  = fmaf(-m1, m1, sxx[v][c]);
            const float s2  = fmaf(-m2, m2, syy[v][c]);
            const float s12 = fmaf(-m1, m2, sxy[v][c]);
            const float m1p = fmaf(0.5f, m1, 0.5f);
            const float m2p = fmaf(0.5f, m2, 0.5f);
            const float csn = fmaf(2.0f, s12, C2x4);
            const float csd = s1 + s2 + C2x4;
            const float t = m1p * m2p;
            const float ln = fmaf(2.0f, t, C1);
            const float ld = fmaf(m1p, m1p, fmaf(m2p, m2p, C1));
            const float ssim = (csn * ln) * __fdividef(1.0f, csd * ld);
            lsum += (orow < 502 && ocol < 502) ? ssim : 0.0f;
        }
    }

#pragma unroll
    for (int off = 16; off > 0; off >>= 1)
        lsum += __shfl_xor_sync(0xffffffffu, lsum, off);

    __shared__ float wsum[BY / 2];
    __shared__ bool is_last;
    const int wid = (ty * BX + tx) >> 5;     // 8 warps
    const int lid = (ty * BX + tx) & 31;
    if (lid == 0) wsum[wid] = lsum;
    __syncthreads();
    if (wid == 0 && lid == 0) {
        float b = 0.0f;
#pragma unroll
        for (int w = 0; w < BY / 2; w++) b += wsum[w];
        const int bi = blockIdx.x + gridDim.x * (blockIdx.y + gridDim.y * blockIdx.z);
        g_partials[bi] = b;
        __threadfence();
        const unsigned int n = atomicAdd(&g_count, 1u);
        is_last = (n == (unsigned int)(NBLOCKS - 1));
    }
    __syncthreads();

    if (is_last) {
        __threadfence();
        const int tid = ty * BX + tx;
        double s = 0.0;
        for (int i = tid; i < NBLOCKS; i += NTHR)
            s += (double)g_partials[i];
#pragma unroll
        for (int off = 16; off > 0; off >>= 1)
            s += __shfl_xor_sync(0xffffffffu, s, off);
        __shared__ double sd[8];
        if (lid == 0) sd[wid] = s;
        __syncthreads();
        if (wid == 0 && lid == 0) {
            double tot = 0.0;
#pragma unroll
            for (int w = 0; w < 8; w++) tot += sd[w];
            out[0] = (float)(tot * inv_count);
            g_count = 0;  // reset for next graph replay
        }
    }
}

extern "C" void kernel_launch(void* const* d_in, const int* in_sizes, int n_in,
                              void* d_out, int out_size) {
    const float* X = (const float*)d_in[0];
    const float* Y = (const float*)d_in[1];
    float* out = (float*)d_out;

    const int images = in_sizes[0] / (512 * 512);  // 96
    const double count = (double)images * 502.0 * 502.0;

    const size_t smem = 5 * NHR * TW * sizeof(float);  // 74240 B
    cudaFuncSetAttribute(ssim_main_kernel,
                         cudaFuncAttributeMaxDynamicSharedMemorySize, (int)smem);

    dim3 grid(GX, GY, images);  // 8 x 11 x 96 = 8448 blocks
    dim3 block(BX, BY);
    ssim_main_kernel<<<grid, block, smem>>>(X, Y, out, 1.0 / count);
}

// round 6
// speedup vs baseline: 1.1513x; 1.0183x over previous
#include <cuda_runtime.h>

// SSIM, fully fused, single kernel. X,Y: f32[32,3,512,512] -> scalar mean SSIM.
//
// Occupancy-first tiling: TW=64 x TH=32, smem [5][42][64] = 53.76KB -> 4 CTAs/SM
// (32 warps). Register budget 64/thread: phase 2 uses 4 vrows x 2 cols = 40 accs.
// Phase 1 (thread map A: 16 col-quads x 16 rows): horizontal 11-tap Gaussian of
//   {x,y,x^2,y^2,xy} -> smem.
// Phase 2 (thread map B: 32 col-pairs x 8 row-groups): vertical 11-tap conv.
// Conv FMAs forced to FFMA-imm SASS form (rt_SMSP=1) via 0f-hex weight literals.
// Epilogue folds [-1,1]->[0,1]: mu' = (mu+1)/2, sigma' = sigma/4.
// Block partials -> __device__ array; last block reduces, writes scalar, resets.

#define TW 64
#define TH 32
#define NHR (TH + 10)   // 42
#define NTHR 256
#define GX 8            // 512/64
#define GY 16           // ceil(502/32)
#define GZ 96
#define NBLOCKS (GX * GY * GZ)

__device__ float g_partials[NBLOCKS];
__device__ unsigned int g_count = 0;

// acc += v * w[k], w[k] an immediate multiplier (FFMA-imm form, rt=1).
__device__ __forceinline__ void fmaw(const int k, const float v, float& a) {
    switch (k) {
    case 0:  asm("fma.rn.f32 %0, %1, 0f3A86CAB5, %0;" : "+f"(a) : "f"(v)); break;
    case 1:  asm("fma.rn.f32 %0, %1, 0f3BF8FF05, %0;" : "+f"(a) : "f"(v)); break;
    case 2:  asm("fma.rn.f32 %0, %1, 0f3D137590, %0;" : "+f"(a) : "f"(v)); break;
    case 3:  asm("fma.rn.f32 %0, %1, 0f3DDFF883, %0;" : "+f"(a) : "f"(v)); break;
    case 4:  asm("fma.rn.f32 %0, %1, 0f3E5A1E20, %0;" : "+f"(a) : "f"(v)); break;
    case 5:  asm("fma.rn.f32 %0, %1, 0f3E8832B1, %0;" : "+f"(a) : "f"(v)); break;
    case 6:  asm("fma.rn.f32 %0, %1, 0f3E5A1E20, %0;" : "+f"(a) : "f"(v)); break;
    case 7:  asm("fma.rn.f32 %0, %1, 0f3DDFF883, %0;" : "+f"(a) : "f"(v)); break;
    case 8:  asm("fma.rn.f32 %0, %1, 0f3D137590, %0;" : "+f"(a) : "f"(v)); break;
    case 9:  asm("fma.rn.f32 %0, %1, 0f3BF8FF05, %0;" : "+f"(a) : "f"(v)); break;
    case 10: asm("fma.rn.f32 %0, %1, 0f3A86CAB5, %0;" : "+f"(a) : "f"(v)); break;
    default: break;
    }
}

__global__ void __launch_bounds__(NTHR, 4)
ssim_main_kernel(const float* __restrict__ X, const float* __restrict__ Y,
                 float* __restrict__ out, double inv_count) {
    extern __shared__ float sh[];  // [5][NHR][TW] = 53760 B

    const int tid = threadIdx.x;
    const int c0 = blockIdx.x * TW;
    const int r0 = blockIdx.y * TH;
    const long img = blockIdx.z;
    const float* __restrict__ Xi = X + img * (512L * 512L);
    const float* __restrict__ Yi = Y + img * (512L * 512L);

    // ---------------- Phase 1: horizontal pass into smem ----------------
    // Map A: 16 col-quads x 16 rows.
    {
        const int q1 = tid & 15;        // col quad
        const int r1 = tid >> 4;        // row 0..15
        const int basec = c0 + 4 * q1;
        for (int hr = r1; hr < NHR; hr += 16) {
            const int gr = r0 + hr;
            const float* __restrict__ xr = Xi + (long)gr * 512;
            const float* __restrict__ yr = Yi + (long)gr * 512;
            const bool rok = (gr < 512);
            float xv[16], yv[16];
#pragma unroll
            for (int q = 0; q < 4; q++) {
                const int qc = basec + 4 * q;
                float4 xq, yq;
                if (rok && qc < 512) {
                    xq = *reinterpret_cast<const float4*>(xr + qc);
                    yq = *reinterpret_cast<const float4*>(yr + qc);
                } else {
                    xq = make_float4(0.f, 0.f, 0.f, 0.f);
                    yq = make_float4(0.f, 0.f, 0.f, 0.f);
                }
                xv[4 * q + 0] = xq.x; xv[4 * q + 1] = xq.y;
                xv[4 * q + 2] = xq.z; xv[4 * q + 3] = xq.w;
                yv[4 * q + 0] = yq.x; yv[4 * q + 1] = yq.y;
                yv[4 * q + 2] = yq.z; yv[4 * q + 3] = yq.w;
            }
            float ax[4], ay[4], axx[4], ayy[4], axy[4];
#pragma unroll
            for (int j = 0; j < 4; j++) {
                ax[j] = 0.f; ay[j] = 0.f; axx[j] = 0.f; ayy[j] = 0.f; axy[j] = 0.f;
            }
#pragma unroll
            for (int t = 0; t < 14; t++) {
                const float xt = xv[t], yt = yv[t];
                const float pxx = xt * xt;
                const float pyy = yt * yt;
                const float pxy = xt * yt;
#pragma unroll
                for (int j = 0; j < 4; j++) {
                    const int k = t - j;
                    if (k >= 0 && k <= 10) {
                        fmaw(k, xt,  ax[j]);
                        fmaw(k, yt,  ay[j]);
                        fmaw(k, pxx, axx[j]);
                        fmaw(k, pyy, ayy[j]);
                        fmaw(k, pxy, axy[j]);
                    }
                }
            }
            const int so = hr * TW + 4 * q1;
            *reinterpret_cast<float4*>(&sh[0 * NHR * TW + so]) = make_float4(ax[0], ax[1], ax[2], ax[3]);
            *reinterpret_cast<float4*>(&sh[1 * NHR * TW + so]) = make_float4(ay[0], ay[1], ay[2], ay[3]);
            *reinterpret_cast<float4*>(&sh[2 * NHR * TW + so]) = make_float4(axx[0], axx[1], axx[2], axx[3]);
            *reinterpret_cast<float4*>(&sh[3 * NHR * TW + so]) = make_float4(ayy[0], ayy[1], ayy[2], ayy[3]);
            *reinterpret_cast<float4*>(&sh[4 * NHR * TW + so]) = make_float4(axy[0], axy[1], axy[2], axy[3]);
        }
    }
    __syncthreads();

    // ---------------- Phase 2: vertical conv, 4 vrows x 2 cols per thread --------
    // Map B: 32 col-pairs x 8 row-groups.
    const int tx2 = tid & 31;       // col pair -> cols 2*tx2, 2*tx2+1
    const int ty2 = tid >> 5;       // 0..7
    const int lr0 = ty2 * 4;        // 8 * 4 = 32 rows
    const int scol = 2 * tx2;

    float mu1[4][2], mu2[4][2], sxx[4][2], syy[4][2], sxy[4][2];
#pragma unroll
    for (int v = 0; v < 4; v++)
#pragma unroll
        for (int c = 0; c < 2; c++) {
            mu1[v][c] = 0.f; mu2[v][c] = 0.f;
            sxx[v][c] = 0.f; syy[v][c] = 0.f; sxy[v][c] = 0.f;
        }

#pragma unroll
    for (int i = 0; i < 14; i++) {   // i = v + k, v in 0..3, k in 0..10
        const int roff = (lr0 + i) * TW + scol;
        {
            const float2 a = *reinterpret_cast<const float2*>(&sh[0 * NHR * TW + roff]);
#pragma unroll
            for (int v = 0; v < 4; v++) {
                const int k = i - v;
                if (k >= 0 && k <= 10) { fmaw(k, a.x, mu1[v][0]); fmaw(k, a.y, mu1[v][1]); }
            }
        }
        {
            const float2 a = *reinterpret_cast<const float2*>(&sh[1 * NHR * TW + roff]);
#pragma unroll
            for (int v = 0; v < 4; v++) {
                const int k = i - v;
                if (k >= 0 && k <= 10) { fmaw(k, a.x, mu2[v][0]); fmaw(k, a.y, mu2[v][1]); }
            }
        }
        {
            const float2 a = *reinterpret_cast<const float2*>(&sh[2 * NHR * TW + roff]);
#pragma unroll
            for (int v = 0; v < 4; v++) {
                const int k = i - v;
                if (k >= 0 && k <= 10) { fmaw(k, a.x, sxx[v][0]); fmaw(k, a.y, sxx[v][1]); }
            }
        }
        {
            const float2 a = *reinterpret_cast<const float2*>(&sh[3 * NHR * TW + roff]);
#pragma unroll
            for (int v = 0; v < 4; v++) {
                const int k = i - v;
                if (k >= 0 && k <= 10) { fmaw(k, a.x, syy[v][0]); fmaw(k, a.y, syy[v][1]); }
            }
        }
        {
            const float2 a = *reinterpret_cast<const float2*>(&sh[4 * NHR * TW + roff]);
#pragma unroll
            for (int v = 0; v < 4; v++) {
                const int k = i - v;
                if (k >= 0 && k <= 10) { fmaw(k, a.x, sxy[v][0]); fmaw(k, a.y, sxy[v][1]); }
            }
        }
    }

    // ---------------- Epilogue + reduction ----------------
    float lsum = 0.0f;
    const float C1 = 1e-4f;      // (0.01)^2
    const float C2x4 = 0.0036f;  // 4*(0.03)^2
#pragma unroll
    for (int v = 0; v < 4; v++) {
        const int orow = r0 + lr0 + v;
#pragma unroll
        for (int c = 0; c < 2; c++) {
            const int ocol = c0 + scol + c;
            const float m1 = mu1[v][c];
            const float m2 = mu2[v][c];
            const float s1  = fmaf(-m1, m1, sxx[v][c]);
            const float s2  = fmaf(-m2, m2, syy[v][c]);
            const float s12 = fmaf(-m1, m2, sxy[v][c]);
            const float m1p = fmaf(0.5f, m1, 0.5f);
            const float m2p = fmaf(0.5f, m2, 0.5f);
            const float csn = fmaf(2.0f, s12, C2x4);
            const float csd = s1 + s2 + C2x4;
            const float t = m1p * m2p;
            const float ln = fmaf(2.0f, t, C1);
            const float ld = fmaf(m1p, m1p, fmaf(m2p, m2p, C1));
            const float ssim = (csn * ln) * __fdividef(1.0f, csd * ld);
            lsum += (orow < 502 && ocol < 502) ? ssim : 0.0f;
        }
    }

#pragma unroll
    for (int off = 16; off > 0; off >>= 1)
        lsum += __shfl_xor_sync(0xffffffffu, lsum, off);

    __shared__ float wsum[8];
    __shared__ bool is_last;
    const int wid = tid >> 5;
    const int lid = tid & 31;
    if (lid == 0) wsum[wid] = lsum;
    __syncthreads();
    if (tid == 0) {
        float b = 0.0f;
#pragma unroll
        for (int w = 0; w < 8; w++) b += wsum[w];
        const int bi = blockIdx.x + gridDim.x * (blockIdx.y + gridDim.y * blockIdx.z);
        g_partials[bi] = b;
        __threadfence();
        const unsigned int n = atomicAdd(&g_count, 1u);
        is_last = (n == (unsigned int)(NBLOCKS - 1));
    }
    __syncthreads();

    if (is_last) {
        __threadfence();
        double s = 0.0;
        for (int i = tid; i < NBLOCKS; i += NTHR)
            s += (double)g_partials[i];
#pragma unroll
        for (int off = 16; off > 0; off >>= 1)
            s += __shfl_xor_sync(0xffffffffu, s, off);
        __shared__ double sd[8];
        if (lid == 0) sd[wid] = s;
        __syncthreads();
        if (tid == 0) {
            double tot = 0.0;
#pragma unroll
            for (int w = 0; w < 8; w++) tot += sd[w];
            out[0] = (float)(tot * inv_count);
            g_count = 0;  // reset for next graph replay
        }
    }
}

extern "C" void kernel_launch(void* const* d_in, const int* in_sizes, int n_in,
                              void* d_out, int out_size) {
    const float* X = (const float*)d_in[0];
    const float* Y = (const float*)d_in[1];
    float* out = (float*)d_out;

    const int images = in_sizes[0] / (512 * 512);  // 96
    const double count = (double)images * 502.0 * 502.0;

    const size_t smem = 5 * NHR * TW * sizeof(float);  // 53760 B
    cudaFuncSetAttribute(ssim_main_kernel,
                         cudaFuncAttributeMaxDynamicSharedMemorySize, (int)smem);

    dim3 grid(GX, GY, images);  // 8 x 16 x 96 = 12288 blocks
    ssim_main_kernel<<<grid, NTHR, smem>>>(X, Y, out, 1.0 / count);
}

// round 7
// speedup vs baseline: 1.1821x; 1.0267x over previous
#include <cuda_runtime.h>

// SSIM, fully fused, single kernel. X,Y: f32[32,3,512,512] -> scalar mean SSIM.
//
// TW=64 x TH=32, smem [5][42][64] = 53.76KB -> 4 CTAs/SM (32 warps), regs <= 64.
// Phase 1 (16 col-quads x 16 rows): horizontal 11-tap Gaussian of {x,y,x2,y2,xy}
//   -> smem, scalar FFMA-imm (rt=1) with 0f-hex weight literals.
// Phase 2 (32 col-pairs x 8 row-groups): vertical 11-tap conv in PACKED f32x2
//   (column pairs straight from LDS.64), two register-light passes, symmetric
//   weight pairs (only 6 held: w[k]=w[10-k]).
// Epilogue folds [-1,1]->[0,1]: mu' = (mu+1)/2, sigma' = sigma/4.
// Block partials -> __device__ array; last block reduces, writes scalar, resets.

#define TW 64
#define TH 32
#define NHR (TH + 10)   // 42
#define NTHR 256
#define GX 8
#define GY 16
#define GZ 96
#define NBLOCKS (GX * GY * GZ)

typedef unsigned long long u64;

__device__ float g_partials[NBLOCKS];
__device__ unsigned int g_count = 0;

// scalar: acc += v * w[k], w[k] immediate multiplier (FFMA-imm, rt=1).
__device__ __forceinline__ void fmaw(const int k, const float v, float& a) {
    switch (k) {
    case 0:  asm("fma.rn.f32 %0, %1, 0f3A86CAB5, %0;" : "+f"(a) : "f"(v)); break;
    case 1:  asm("fma.rn.f32 %0, %1, 0f3BF8FF05, %0;" : "+f"(a) : "f"(v)); break;
    case 2:  asm("fma.rn.f32 %0, %1, 0f3D137590, %0;" : "+f"(a) : "f"(v)); break;
    case 3:  asm("fma.rn.f32 %0, %1, 0f3DDFF883, %0;" : "+f"(a) : "f"(v)); break;
    case 4:  asm("fma.rn.f32 %0, %1, 0f3E5A1E20, %0;" : "+f"(a) : "f"(v)); break;
    case 5:  asm("fma.rn.f32 %0, %1, 0f3E8832B1, %0;" : "+f"(a) : "f"(v)); break;
    case 6:  asm("fma.rn.f32 %0, %1, 0f3E5A1E20, %0;" : "+f"(a) : "f"(v)); break;
    case 7:  asm("fma.rn.f32 %0, %1, 0f3DDFF883, %0;" : "+f"(a) : "f"(v)); break;
    case 8:  asm("fma.rn.f32 %0, %1, 0f3D137590, %0;" : "+f"(a) : "f"(v)); break;
    case 9:  asm("fma.rn.f32 %0, %1, 0f3BF8FF05, %0;" : "+f"(a) : "f"(v)); break;
    case 10: asm("fma.rn.f32 %0, %1, 0f3A86CAB5, %0;" : "+f"(a) : "f"(v)); break;
    default: break;
    }
}

__device__ __forceinline__ u64 pk2(float lo, float hi) {
    u64 r;
    asm("mov.b64 %0, {%1, %2};" : "=l"(r) : "f"(lo), "f"(hi));
    return r;
}
__device__ __forceinline__ void upk2(float& lo, float& hi, u64 v) {
    asm("mov.b64 {%0, %1}, %2;" : "=f"(lo), "=f"(hi) : "l"(v));
}
__device__ __forceinline__ u64 fma2(u64 a, u64 b, u64 c) {
    u64 d;
    asm("fma.rn.f32x2 %0, %1, %2, %3;" : "=l"(d) : "l"(a), "l"(b), "l"(c));
    return d;
}

// Gaussian(11, sigma=1.5) weights (host/device constexpr).
__device__ __host__ __forceinline__ constexpr float gwe(int k) {
    return (k == 0 || k == 10) ? 0.00102838f
         : (k == 1 || k == 9)  ? 0.00759876f
         : (k == 2 || k == 8)  ? 0.03600079f
         : (k == 3 || k == 7)  ? 0.10936072f
         : (k == 4 || k == 6)  ? 0.21300555f
         : (k == 5)            ? 0.26601173f
         : 0.0f;
}

__global__ void __launch_bounds__(NTHR, 4)
ssim_main_kernel(const float* __restrict__ X, const float* __restrict__ Y,
                 float* __restrict__ out, double inv_count) {
    extern __shared__ float sh[];  // [5][NHR][TW] = 53760 B

    const int tid = threadIdx.x;
    const int c0 = blockIdx.x * TW;
    const int r0 = blockIdx.y * TH;
    const long img = blockIdx.z;
    const float* __restrict__ Xi = X + img * (512L * 512L);
    const float* __restrict__ Yi = Y + img * (512L * 512L);

    // ---------------- Phase 1: horizontal pass into smem (scalar FFMA-imm) ------
    {
        const int q1 = tid & 15;
        const int r1 = tid >> 4;
        const int basec = c0 + 4 * q1;
        for (int hr = r1; hr < NHR; hr += 16) {
            const int gr = r0 + hr;
            const float* __restrict__ xr = Xi + (long)gr * 512;
            const float* __restrict__ yr = Yi + (long)gr * 512;
            const bool rok = (gr < 512);
            float xv[16], yv[16];
#pragma unroll
            for (int q = 0; q < 4; q++) {
                const int qc = basec + 4 * q;
                float4 xq, yq;
                if (rok && qc < 512) {
                    xq = *reinterpret_cast<const float4*>(xr + qc);
                    yq = *reinterpret_cast<const float4*>(yr + qc);
                } else {
                    xq = make_float4(0.f, 0.f, 0.f, 0.f);
                    yq = make_float4(0.f, 0.f, 0.f, 0.f);
                }
                xv[4 * q + 0] = xq.x; xv[4 * q + 1] = xq.y;
                xv[4 * q + 2] = xq.z; xv[4 * q + 3] = xq.w;
                yv[4 * q + 0] = yq.x; yv[4 * q + 1] = yq.y;
                yv[4 * q + 2] = yq.z; yv[4 * q + 3] = yq.w;
            }
            float ax[4], ay[4], axx[4], ayy[4], axy[4];
#pragma unroll
            for (int j = 0; j < 4; j++) {
                ax[j] = 0.f; ay[j] = 0.f; axx[j] = 0.f; ayy[j] = 0.f; axy[j] = 0.f;
            }
#pragma unroll
            for (int t = 0; t < 14; t++) {
                const float xt = xv[t], yt = yv[t];
                const float pxx = xt * xt;
                const float pyy = yt * yt;
                const float pxy = xt * yt;
#pragma unroll
                for (int j = 0; j < 4; j++) {
                    const int k = t - j;
                    if (k >= 0 && k <= 10) {
                        fmaw(k, xt,  ax[j]);
                        fmaw(k, yt,  ay[j]);
                        fmaw(k, pxx, axx[j]);
                        fmaw(k, pyy, ayy[j]);
                        fmaw(k, pxy, axy[j]);
                    }
                }
            }
            const int so = hr * TW + 4 * q1;
            *reinterpret_cast<float4*>(&sh[0 * NHR * TW + so]) = make_float4(ax[0], ax[1], ax[2], ax[3]);
            *reinterpret_cast<float4*>(&sh[1 * NHR * TW + so]) = make_float4(ay[0], ay[1], ay[2], ay[3]);
            *reinterpret_cast<float4*>(&sh[2 * NHR * TW + so]) = make_float4(axx[0], axx[1], axx[2], axx[3]);
            *reinterpret_cast<float4*>(&sh[3 * NHR * TW + so]) = make_float4(ayy[0], ayy[1], ayy[2], ayy[3]);
            *reinterpret_cast<float4*>(&sh[4 * NHR * TW + so]) = make_float4(axy[0], axy[1], axy[2], axy[3]);
        }
    }
    __syncthreads();

    // ---------------- Phase 2: vertical conv, packed f32x2, 4 vrows x 1 colpair --
    const int tx2 = tid & 31;
    const int ty2 = tid >> 5;
    const int lr0 = ty2 * 4;
    const int scol = 2 * tx2;

    // 6 broadcast weight pairs (symmetry: w[k] = w[10-k]).
    u64 WB[6];
#pragma unroll
    for (int k = 0; k < 6; k++) WB[k] = pk2(gwe(k), gwe(k));

    // Pass A: mu1, mu2 (8 u64 accs).
    u64 amu1[4], amu2[4];
#pragma unroll
    for (int v = 0; v < 4; v++) { amu1[v] = 0ull; amu2[v] = 0ull; }

#pragma unroll
    for (int i = 0; i < 14; i++) {
        const int roff = (lr0 + i) * TW + scol;
        const u64 d0 = *reinterpret_cast<const u64*>(&sh[0 * NHR * TW + roff]);
        const u64 d1 = *reinterpret_cast<const u64*>(&sh[1 * NHR * TW + roff]);
#pragma unroll
        for (int v = 0; v < 4; v++) {
            const int k = i - v;
            if (k >= 0 && k <= 10) {
                const u64 w = WB[k <= 5 ? k : 10 - k];
                amu1[v] = fma2(d0, w, amu1[v]);
                amu2[v] = fma2(d1, w, amu2[v]);
            }
        }
    }

    // Pass B: sxx, syy, sxy (12 u64 accs).
    u64 asxx[4], asyy[4], asxy[4];
#pragma unroll
    for (int v = 0; v < 4; v++) { asxx[v] = 0ull; asyy[v] = 0ull; asxy[v] = 0ull; }

#pragma unroll
    for (int i = 0; i < 14; i++) {
        const int roff = (lr0 + i) * TW + scol;
        const u64 d2 = *reinterpret_cast<const u64*>(&sh[2 * NHR * TW + roff]);
        const u64 d3 = *reinterpret_cast<const u64*>(&sh[3 * NHR * TW + roff]);
        const u64 d4 = *reinterpret_cast<const u64*>(&sh[4 * NHR * TW + roff]);
#pragma unroll
        for (int v = 0; v < 4; v++) {
            const int k = i - v;
            if (k >= 0 && k <= 10) {
                const u64 w = WB[k <= 5 ? k : 10 - k];
                asxx[v] = fma2(d2, w, asxx[v]);
                asyy[v] = fma2(d3, w, asyy[v]);
                asxy[v] = fma2(d4, w, asxy[v]);
            }
        }
    }

    // ---------------- Epilogue + reduction ----------------
    float lsum = 0.0f;
    const float C1 = 1e-4f;      // (0.01)^2
    const float C2x4 = 0.0036f;  // 4*(0.03)^2
#pragma unroll
    for (int v = 0; v < 4; v++) {
        const int orow = r0 + lr0 + v;
        float m1l, m1h, m2l, m2h, xxl, xxh, yyl, yyh, xyl, xyh;
        upk2(m1l, m1h, amu1[v]);
        upk2(m2l, m2h, amu2[v]);
        upk2(xxl, xxh, asxx[v]);
        upk2(yyl, yyh, asyy[v]);
        upk2(xyl, xyh, asxy[v]);
#pragma unroll
        for (int c = 0; c < 2; c++) {
            const int ocol = c0 + scol + c;
            const float m1 = c ? m1h : m1l;
            const float m2 = c ? m2h : m2l;
            const float xx = c ? xxh : xxl;
            const float yy = c ? yyh : yyl;
            const float xy = c ? xyh : xyl;
            const float s1  = fmaf(-m1, m1, xx);
            const float s2  = fmaf(-m2, m2, yy);
            const float s12 = fmaf(-m1, m2, xy);
            const float m1p = fmaf(0.5f, m1, 0.5f);
            const float m2p = fmaf(0.5f, m2, 0.5f);
            const float csn = fmaf(2.0f, s12, C2x4);
            const float csd = s1 + s2 + C2x4;
            const float t = m1p * m2p;
            const float ln = fmaf(2.0f, t, C1);
            const float ld = fmaf(m1p, m1p, fmaf(m2p, m2p, C1));
            const float ssim = (csn * ln) * __fdividef(1.0f, csd * ld);
            lsum += (orow < 502 && ocol < 502) ? ssim : 0.0f;
        }
    }

#pragma unroll
    for (int off = 16; off > 0; off >>= 1)
        lsum += __shfl_xor_sync(0xffffffffu, lsum, off);

    __shared__ float wsum[8];
    __shared__ bool is_last;
    const int wid = tid >> 5;
    const int lid = tid & 31;
    if (lid == 0) wsum[wid] = lsum;
    __syncthreads();
    if (tid == 0) {
        float b = 0.0f;
#pragma unroll
        for (int w = 0; w < 8; w++) b += wsum[w];
        const int bi = blockIdx.x + gridDim.x * (blockIdx.y + gridDim.y * blockIdx.z);
        g_partials[bi] = b;
        __threadfence();
        const unsigned int n = atomicAdd(&g_count, 1u);
        is_last = (n == (unsigned int)(NBLOCKS - 1));
    }
    __syncthreads();

    if (is_last) {
        __threadfence();
        double s = 0.0;
        for (int i = tid; i < NBLOCKS; i += NTHR)
            s += (double)g_partials[i];
#pragma unroll
        for (int off = 16; off > 0; off >>= 1)
            s += __shfl_xor_sync(0xffffffffu, s, off);
        __shared__ double sd[8];
        if (lid == 0) sd[wid] = s;
        __syncthreads();
        if (tid == 0) {
            double tot = 0.0;
#pragma unroll
            for (int w = 0; w < 8; w++) tot += sd[w];
            out[0] = (float)(tot * inv_count);
            g_count = 0;  // reset for next graph replay
        }
    }
}

extern "C" void kernel_launch(void* const* d_in, const int* in_sizes, int n_in,
                              void* d_out, int out_size) {
    const float* X = (const float*)d_in[0];
    const float* Y = (const float*)d_in[1];
    float* out = (float*)d_out;

    const int images = in_sizes[0] / (512 * 512);  // 96
    const double count = (double)images * 502.0 * 502.0;

    const size_t smem = 5 * NHR * TW * sizeof(float);  // 53760 B
    cudaFuncSetAttribute(ssim_main_kernel,
                         cudaFuncAttributeMaxDynamicSharedMemorySize, (int)smem);

    dim3 grid(GX, GY, images);  // 12288 blocks
    ssim_main_kernel<<<grid, NTHR, smem>>>(X, Y, out, 1.0 / count);
}